// round 15
// baseline (speedup 1.0000x reference)
#include <cuda_runtime.h>
#include <cuda_fp16.h>
#include <cstdint>

#define IC1 10
#define OC1 64
#define OC2 128
#define NB  64          // 2 images x 32 batch
#define M0  0.03f       // pre-BN ambiguity margin for fp16 accumulation

__device__ int      g_cnt[NB][OC1][9];   // S, Rf, Rl, Cf, Cl, q_tl, q_tr, q_bl, q_br
__device__ float    g_s2[NB][OC2];
__device__ float    g_inv1[OC1],  g_beta1[OC1];
__device__ float    g_inv2[OC2],  g_beta2[OC2];
__device__ __align__(16) uint32_t g_Wp[90 * 32];  // half2 oc-pairs (w[2o],w[2o+1]), [tap][ocpair]

// dynamic smem layout (bytes)
#define SM_W    0        // u32[90*32] = 11520
#define SM_IN   11520    // float[6120] = 24480
#define SM_SPK  36000    // uchar[64*128] = 8192
#define SM_LC   44192    // int[4]
#define SM_LIST 44208    // u16[8192] = 16384 (worst-case exact capacity)
#define SMEM_BYTES 60592

// ---------------------------------------------------------------------------
// nop kernel (launch-slot shims so ncu's 4th-kernel profile lands on stageA)
// ---------------------------------------------------------------------------
__global__ void nop_kernel() {}

// ---------------------------------------------------------------------------
// prep: zero counters, fold BN params, build half2 oc-pair weight table
// ---------------------------------------------------------------------------
__global__ void prep_kernel(const float* __restrict__ w1,
                            const float* __restrict__ g1, const float* __restrict__ b1,
                            const float* __restrict__ m1, const float* __restrict__ v1,
                            const float* __restrict__ g2, const float* __restrict__ b2,
                            const float* __restrict__ m2, const float* __restrict__ v2) {
    int gid = blockIdx.x * blockDim.x + threadIdx.x;
    int* c = &g_cnt[0][0][0];
    for (int i = gid; i < NB * OC1 * 9; i += gridDim.x * blockDim.x) c[i] = 0;
    if (blockIdx.x == 0) {
        int t = threadIdx.x;
        if (t < OC1) {
            float inv = g1[t] / sqrtf(v1[t] + 1e-5f);
            g_inv1[t] = inv;
            g_beta1[t] = b1[t] - m1[t] * inv;
        }
        if (t < OC2) {
            float inv = g2[t] / sqrtf(v2[t] + 1e-5f);
            g_inv2[t] = inv;
            g_beta2[t] = b2[t] - m2[t] * inv;
        }
    }
    if (gid < 90 * 32) {
        int r = gid >> 5, op = gid & 31;
        __half h0 = __float2half_rn(__ldg(&w1[(2 * op) * 90 + r]));
        __half h1 = __float2half_rn(__ldg(&w1[(2 * op + 1) * 90 + r]));
        __half2 d = __halves2half2(h0, h1);
        g_Wp[r * 32 + op] = *reinterpret_cast<uint32_t*>(&d);
    }
}

// ---------------------------------------------------------------------------
// stage A: conv1 via HFMA2 — oc-pair weights (no dup ops in mainloop),
//          inputs dup-packed once in prologue. BN + maxpool2 + margin spike
//          + exact in-block fp32 fixup.
// grid (8, 16, 64), block 128. Thread = one pooled window for all 64 oc.
// ---------------------------------------------------------------------------
__global__ __launch_bounds__(128, 2) void stageA_kernel(const float* __restrict__ x0,
                                                        const float* __restrict__ x1,
                                                        const float* __restrict__ w1) {
    extern __shared__ char smem[];
    uint32_t*      s_wp  = (uint32_t*)(smem + SM_W);
    float*         s_in  = (float*)(smem + SM_IN);
    unsigned char* spk   = (unsigned char*)(smem + SM_SPK);
    int*           sLC   = (int*)(smem + SM_LC);
    uint16_t*      sList = (uint16_t*)(smem + SM_LIST);

    const int tid = threadIdx.x;
    const int bx = blockIdx.x, by = blockIdx.y, n = blockIdx.z;
    const float* __restrict__ x = (n < 32) ? x0 : x1;
    const int b = n & 31;

    // load oc-pair weight table (2880 u32 = 720 uint4)
    {
        const uint4* gw = (const uint4*)g_Wp;
        uint4* sw4 = (uint4*)s_wp;
        for (int i = tid; i < 720; i += 128) sw4[i] = __ldg(&gw[i]);
    }
    if (tid == 0) sLC[0] = 0;

    // stage input tile fp32 (18 x 34 per ic), SAME zero padding
    const int iy0 = by * 16 - 1;
    const int ix0 = bx * 32 - 1;
    for (int i = tid; i < IC1 * 612; i += 128) {
        int ic = i / 612, r2 = i % 612;
        int rw = r2 / 34, cl = r2 % 34;
        int gy = iy0 + rw, gx = ix0 + cl;
        float v = 0.f;
        if ((unsigned)gy < 256u && (unsigned)gx < 256u)
            v = __ldg(&x[((b * IC1 + ic) * 256 + gy) * 256 + gx]);
        s_in[i] = v;
    }
    __syncthreads();

    const int lpx = tid & 15, lpy = tid >> 4;
    const int rr = 2 * lpy, cc = 2 * lpx;

    // prologue: dup-pack ALL 4x4 input values per ic once: hd[ic*16 + i*4+j] = (v,v)
    uint32_t hd[IC1 * 16];
#pragma unroll
    for (int ic = 0; ic < IC1; ++ic) {
#pragma unroll
        for (int i = 0; i < 4; ++i) {
            const float2* p = (const float2*)&s_in[ic * 612 + (rr + i) * 34 + cc];
            float2 u = p[0], w = p[1];
            float rv[4] = {u.x, u.y, w.x, w.y};
#pragma unroll
            for (int j = 0; j < 4; ++j) {
                __half2 h = __half2half2(__float2half_rn(rv[j]));
                hd[ic * 16 + i * 4 + j] = *reinterpret_cast<uint32_t*>(&h);
            }
        }
    }

    const uint4* s_wp4 = (const uint4*)s_wp;

    // oc-group sweep: 8 oc (4 pairs) per g; pure LDS.128 + HFMA2 mainloop
#pragma unroll 1
    for (int g = 0; g < 8; ++g) {
        __half2 acc[4][4];   // [ocpair][pos]; pos = dy*2+dx
#pragma unroll
        for (int p = 0; p < 4; ++p)
#pragma unroll
            for (int q = 0; q < 4; ++q) acc[p][q] = __half2half2(__ushort_as_half(0));

#pragma unroll
        for (int ic = 0; ic < IC1; ++ic) {
#pragma unroll
            for (int k = 0; k < 9; ++k) {
                const int ky = k / 3, kx = k % 3;
                // one broadcast LDS.128: 4 oc-pairs (ocs 8g..8g+7) for this tap
                uint4 wv = s_wp4[(ic * 9 + k) * 8 + g];
                uint32_t wq[4] = {wv.x, wv.y, wv.z, wv.w};
                __half2 v00 = *reinterpret_cast<__half2*>(&hd[ic * 16 + ky * 4 + kx]);
                __half2 v01 = *reinterpret_cast<__half2*>(&hd[ic * 16 + ky * 4 + kx + 1]);
                __half2 v10 = *reinterpret_cast<__half2*>(&hd[ic * 16 + (ky + 1) * 4 + kx]);
                __half2 v11 = *reinterpret_cast<__half2*>(&hd[ic * 16 + (ky + 1) * 4 + kx + 1]);
#pragma unroll
                for (int p = 0; p < 4; ++p) {
                    __half2 w = *reinterpret_cast<__half2*>(&wq[p]);
                    acc[p][0] = __hfma2(w, v00, acc[p][0]);
                    acc[p][1] = __hfma2(w, v01, acc[p][1]);
                    acc[p][2] = __hfma2(w, v10, acc[p][2]);
                    acc[p][3] = __hfma2(w, v11, acc[p][3]);
                }
            }
        }
        // epilogue: BN + pool max + margin classify (per oc in the pair)
#pragma unroll
        for (int p = 0; p < 4; ++p) {
            float lo[4], hi[4];
#pragma unroll
            for (int q = 0; q < 4; ++q) {
                lo[q] = __low2float(acc[p][q]);
                hi[q] = __high2float(acc[p][q]);
            }
#pragma unroll
            for (int s2 = 0; s2 < 2; ++s2) {
                const int oc = g * 8 + 2 * p + s2;
                const float* v = s2 ? hi : lo;
                float mx = fmaxf(fmaxf(v[0], v[1]), fmaxf(v[2], v[3]));
                float mn = fminf(fminf(v[0], v[1]), fminf(v[2], v[3]));
                float inv = __ldg(&g_inv1[oc]);
                float bet = __ldg(&g_beta1[oc]);
                float zb = (inv >= 0.f ? mx : mn) * inv + bet;
                float Mz = M0 * fabsf(inv);
                unsigned char s = 0;
                if (zb - Mz > 1.0f) s = 1;
                else if (zb + Mz > 1.0f) {
                    int ix = atomicAdd(&sLC[0], 1);
                    sList[ix] = (uint16_t)(tid * 64 + oc);
                }
                spk[oc * 128 + tid] = s;
            }
        }
    }
    __syncthreads();

    // exact fp32 fixup of ambiguous windows from the staged fp32 tile
    {
        const int cnt = sLC[0];
        for (int i = tid; i < cnt; i += 128) {
            const int e = sList[i];
            const int q = e >> 6, oc = e & 63;
            const int r0 = 2 * (q >> 4), c0 = 2 * (q & 15);
            float a0 = 0.f, a1 = 0.f, a2 = 0.f, a3 = 0.f;
#pragma unroll 1
            for (int ic = 0; ic < IC1; ++ic) {
                float v[4][4];
#pragma unroll
                for (int iy = 0; iy < 4; ++iy)
#pragma unroll
                    for (int ixx = 0; ixx < 4; ++ixx)
                        v[iy][ixx] = s_in[ic * 612 + (r0 + iy) * 34 + (c0 + ixx)];
                const float* wr = w1 + oc * 90 + ic * 9;
#pragma unroll
                for (int ky = 0; ky < 3; ++ky)
#pragma unroll
                    for (int kx = 0; kx < 3; ++kx) {
                        float wv = __ldg(&wr[ky * 3 + kx]);
                        a0 = fmaf(wv, v[ky][kx],         a0);
                        a1 = fmaf(wv, v[ky][kx + 1],     a1);
                        a2 = fmaf(wv, v[ky + 1][kx],     a2);
                        a3 = fmaf(wv, v[ky + 1][kx + 1], a3);
                    }
            }
            const float inv = __ldg(&g_inv1[oc]), bet = __ldg(&g_beta1[oc]);
            float zm = fmaxf(fmaxf(fmaf(a0, inv, bet), fmaf(a1, inv, bet)),
                             fmaxf(fmaf(a2, inv, bet), fmaf(a3, inv, bet)));
            spk[oc * 128 + q] = (zm > 1.0f);
        }
    }
    __syncthreads();

    // reduce spike map -> the 9 aggregates
    if (tid < 64) {
        const int oc = tid;
        const int* row = (const int*)&spk[oc * 128];
        int S = 0;
#pragma unroll
        for (int j = 0; j < 32; ++j) S = __dp4a(row[j], 0x01010101, S);
        if (S) atomicAdd(&g_cnt[n][oc][0], S);
        if (by == 0) {      // pooled row 0 lives at lpy==0 -> q 0..15
            int Rf = 0;
#pragma unroll
            for (int j = 0; j < 4; ++j) Rf = __dp4a(row[j], 0x01010101, Rf);
            if (Rf) atomicAdd(&g_cnt[n][oc][1], Rf);
        }
        if (by == 15) {     // pooled row 127 at lpy==7 -> q 112..127
            int Rl = 0;
#pragma unroll
            for (int j = 28; j < 32; ++j) Rl = __dp4a(row[j], 0x01010101, Rl);
            if (Rl) atomicAdd(&g_cnt[n][oc][2], Rl);
        }
        if (bx == 0) {      // col 0 at lpx==0 -> q = 16*lpy
            int Cf = 0;
#pragma unroll
            for (int j = 0; j < 8; ++j) Cf += spk[oc * 128 + 16 * j];
            if (Cf) atomicAdd(&g_cnt[n][oc][3], Cf);
        }
        if (bx == 7) {      // col 127 at lpx==15 -> q = 16*lpy + 15
            int Cl = 0;
#pragma unroll
            for (int j = 0; j < 8; ++j) Cl += spk[oc * 128 + 16 * j + 15];
            if (Cl) atomicAdd(&g_cnt[n][oc][4], Cl);
        }
        if (by == 0 && bx == 0 && spk[oc * 128 + 0])     g_cnt[n][oc][5] = 1;
        if (by == 0 && bx == 7 && spk[oc * 128 + 15])    g_cnt[n][oc][6] = 1;
        if (by == 15 && bx == 0 && spk[oc * 128 + 112])  g_cnt[n][oc][7] = 1;
        if (by == 15 && bx == 7 && spk[oc * 128 + 127])  g_cnt[n][oc][8] = 1;
    }
}

// ---------------------------------------------------------------------------
// stage B: analytic conv2-mean via T aggregates, BN2, spike -> g_s2
// ---------------------------------------------------------------------------
__global__ __launch_bounds__(256) void stageB_kernel(const float* __restrict__ w2) {
    __shared__ __align__(16) float sT[OC1 * 9];
    const int n = blockIdx.x, tid = threadIdx.x;
    const int lane = tid & 31, warp = tid >> 5;
    if (tid < OC1) {
        const int* c = g_cnt[n][tid];
        int S = c[0], Rf = c[1], Rl = c[2], Cf = c[3], Cl = c[4];
        int Re[3] = {Rl, 0, Rf};
        int Ce[3] = {Cl, 0, Cf};
        int Q[9]  = {c[8], 0, c[7],  0, 0, 0,  c[6], 0, c[5]};
#pragma unroll
        for (int k = 0; k < 9; ++k)
            sT[tid * 9 + k] = (float)(S - Re[k / 3] - Ce[k % 3] + Q[k]);
    }
    __syncthreads();
#pragma unroll 1
    for (int i = 0; i < 16; ++i) {
        const int o = warp * 16 + i;
        const float* wr = w2 + o * 576;
        float acc = 0.f;
#pragma unroll
        for (int t = 0; t < 18; ++t) {
            int j = t * 32 + lane;
            acc = fmaf(__ldg(&wr[j]), sT[j], acc);
        }
#pragma unroll
        for (int s = 16; s; s >>= 1) acc += __shfl_xor_sync(0xffffffffu, acc, s);
        if (lane == 0) {
            float z = acc * (1.f / 16384.f);
            z = z * g_inv2[o] + g_beta2[o];
            g_s2[n][o] = (z > 1.f) ? 1.f : 0.f;
        }
    }
}

// ---------------------------------------------------------------------------
// stage C: feat = |s0 - s1|, fc1+relu, fc2  -> out (32,5)
// ---------------------------------------------------------------------------
__global__ __launch_bounds__(256) void stageC_kernel(const float* __restrict__ fc1w,
                                                     const float* __restrict__ fc1b,
                                                     const float* __restrict__ fc2w,
                                                     const float* __restrict__ fc2b,
                                                     float* __restrict__ out) {
    __shared__ float f[128];
    __shared__ float h[64];
    const int n = blockIdx.x, tid = threadIdx.x;
    const int lane = tid & 31, warp = tid >> 5;
    if (tid < 128) f[tid] = fabsf(g_s2[n][tid] - g_s2[n + 32][tid]);
    __syncthreads();
#pragma unroll 1
    for (int i = 0; i < 8; ++i) {
        const int k = warp * 8 + i;
        const float* wr = fc1w + k * 128;
        float acc = 0.f;
#pragma unroll
        for (int t = 0; t < 4; ++t) {
            int j = t * 32 + lane;
            acc = fmaf(__ldg(&wr[j]), f[j], acc);
        }
#pragma unroll
        for (int s = 16; s; s >>= 1) acc += __shfl_xor_sync(0xffffffffu, acc, s);
        if (lane == 0) h[k] = fmaxf(acc + fc1b[k], 0.f);
    }
    __syncthreads();
    if (warp == 0) {
#pragma unroll 1
        for (int c = 0; c < 5; ++c) {
            const float* wr = fc2w + c * 64;
            float acc = fmaf(__ldg(&wr[lane]), h[lane], 0.f);
            acc = fmaf(__ldg(&wr[lane + 32]), h[lane + 32], acc);
#pragma unroll
            for (int s = 16; s; s >>= 1) acc += __shfl_xor_sync(0xffffffffu, acc, s);
            if (lane == 0) out[n * 5 + c] = acc + fc2b[c];
        }
    }
}

extern "C" void kernel_launch(void* const* d_in, const int* in_sizes, int n_in,
                              void* d_out, int out_size) {
    const float* x0   = (const float*)d_in[0];
    const float* x1   = (const float*)d_in[1];
    const float* w1   = (const float*)d_in[2];
    const float* b1g  = (const float*)d_in[3];
    const float* b1b  = (const float*)d_in[4];
    const float* b1m  = (const float*)d_in[5];
    const float* b1v  = (const float*)d_in[6];
    const float* w2   = (const float*)d_in[7];
    const float* b2g  = (const float*)d_in[8];
    const float* b2b  = (const float*)d_in[9];
    const float* b2m  = (const float*)d_in[10];
    const float* b2v  = (const float*)d_in[11];
    const float* fc1w = (const float*)d_in[12];
    const float* fc1b = (const float*)d_in[13];
    const float* fc2w = (const float*)d_in[14];
    const float* fc2b = (const float*)d_in[15];

    cudaFuncSetAttribute(stageA_kernel,
                         cudaFuncAttributeMaxDynamicSharedMemorySize, SMEM_BYTES);

    prep_kernel<<<32, 256>>>(w1, b1g, b1b, b1m, b1v, b2g, b2b, b2m, b2v);
    nop_kernel<<<1, 32>>>();   // shim: put stageA in ncu's profiled (4th) slot
    nop_kernel<<<1, 32>>>();
    dim3 gridA(8, 16, 64);
    stageA_kernel<<<gridA, 128, SMEM_BYTES>>>(x0, x1, w1);
    stageB_kernel<<<64, 256>>>(w2);
    stageC_kernel<<<32, 256>>>(fc1w, fc1b, fc2w, fc2b, (float*)d_out);
}

// round 16
// speedup vs baseline: 1.3142x; 1.3142x over previous
#include <cuda_runtime.h>
#include <cuda_fp16.h>
#include <cstdint>

#define IC1 10
#define OC1 64
#define OC2 128
#define NB  64          // 2 images x 32 batch
#define M0  0.03f       // pre-BN ambiguity margin for fp16 accumulation

__device__ int      g_cnt[NB][OC1][9];   // S, Rf, Rl, Cf, Cl, q_tl, q_tr, q_bl, q_br
__device__ float    g_s2[NB][OC2];
__device__ float    g_inv1[OC1],  g_beta1[OC1];
__device__ float    g_inv2[OC2],  g_beta2[OC2];
__device__ __align__(16) uint32_t g_Wp[90 * 32];  // half2 oc-pairs (w[2o],w[2o+1]), [tap][ocpair]

// dynamic smem layout (bytes)
#define SM_W    0        // u32[90*32] = 11520
#define SM_IN   11520    // float[6120] = 24480
#define SM_SPK  36000    // uchar[64*128] = 8192
#define SM_LC   44192    // int[4]
#define SM_LIST 44208    // u16[8192] = 16384 (worst-case exact capacity)
#define SMEM_BYTES 60592

// ---------------------------------------------------------------------------
// nop kernel (launch-slot shims so ncu's 4th-kernel profile lands on stageA)
// ---------------------------------------------------------------------------
__global__ void nop_kernel() {}

// ---------------------------------------------------------------------------
// prep: zero counters, fold BN params, build half2 oc-pair weight table
// ---------------------------------------------------------------------------
__global__ void prep_kernel(const float* __restrict__ w1,
                            const float* __restrict__ g1, const float* __restrict__ b1,
                            const float* __restrict__ m1, const float* __restrict__ v1,
                            const float* __restrict__ g2, const float* __restrict__ b2,
                            const float* __restrict__ m2, const float* __restrict__ v2) {
    int gid = blockIdx.x * blockDim.x + threadIdx.x;
    int* c = &g_cnt[0][0][0];
    for (int i = gid; i < NB * OC1 * 9; i += gridDim.x * blockDim.x) c[i] = 0;
    if (blockIdx.x == 0) {
        int t = threadIdx.x;
        if (t < OC1) {
            float inv = g1[t] / sqrtf(v1[t] + 1e-5f);
            g_inv1[t] = inv;
            g_beta1[t] = b1[t] - m1[t] * inv;
        }
        if (t < OC2) {
            float inv = g2[t] / sqrtf(v2[t] + 1e-5f);
            g_inv2[t] = inv;
            g_beta2[t] = b2[t] - m2[t] * inv;
        }
    }
    if (gid < 90 * 32) {
        int r = gid >> 5, op = gid & 31;
        __half h0 = __float2half_rn(__ldg(&w1[(2 * op) * 90 + r]));
        __half h1 = __float2half_rn(__ldg(&w1[(2 * op + 1) * 90 + r]));
        __half2 d = __halves2half2(h0, h1);
        g_Wp[r * 32 + op] = *reinterpret_cast<uint32_t*>(&d);
    }
}

// ---------------------------------------------------------------------------
// stage A: conv1 via HFMA2 — ic-outer / all-64-oc-inner. Persistent 128-reg
//          half2 accumulator, transient 16-reg input dups per ic. One
//          broadcast LDS.128 per (ic,tap,4-ocpair); zero dup ops in mainloop.
//          BN + maxpool2 + margin spike + exact in-block fp32 fixup.
// grid (8, 16, 64), block 128. Thread = one pooled window for all 64 oc.
// ---------------------------------------------------------------------------
__global__ __launch_bounds__(128, 2) void stageA_kernel(const float* __restrict__ x0,
                                                        const float* __restrict__ x1,
                                                        const float* __restrict__ w1) {
    extern __shared__ char smem[];
    uint32_t*      s_wp  = (uint32_t*)(smem + SM_W);
    float*         s_in  = (float*)(smem + SM_IN);
    unsigned char* spk   = (unsigned char*)(smem + SM_SPK);
    int*           sLC   = (int*)(smem + SM_LC);
    uint16_t*      sList = (uint16_t*)(smem + SM_LIST);

    const int tid = threadIdx.x;
    const int bx = blockIdx.x, by = blockIdx.y, n = blockIdx.z;
    const float* __restrict__ x = (n < 32) ? x0 : x1;
    const int b = n & 31;

    // load oc-pair weight table (2880 u32 = 720 uint4)
    {
        const uint4* gw = (const uint4*)g_Wp;
        uint4* sw4 = (uint4*)s_wp;
        for (int i = tid; i < 720; i += 128) sw4[i] = __ldg(&gw[i]);
    }
    if (tid == 0) sLC[0] = 0;

    // stage input tile fp32 (18 x 34 per ic), SAME zero padding
    const int iy0 = by * 16 - 1;
    const int ix0 = bx * 32 - 1;
    for (int i = tid; i < IC1 * 612; i += 128) {
        int ic = i / 612, r2 = i % 612;
        int rw = r2 / 34, cl = r2 % 34;
        int gy = iy0 + rw, gx = ix0 + cl;
        float v = 0.f;
        if ((unsigned)gy < 256u && (unsigned)gx < 256u)
            v = __ldg(&x[((b * IC1 + ic) * 256 + gy) * 256 + gx]);
        s_in[i] = v;
    }
    __syncthreads();

    const int lpx = tid & 15, lpy = tid >> 4;
    const int rr = 2 * lpy, cc = 2 * lpx;
    const uint4* s_wp4 = (const uint4*)s_wp;

    // persistent accumulator: 32 oc-pairs x 4 pool positions (128 half2 regs)
    __half2 acc[32][4];
#pragma unroll
    for (int op = 0; op < 32; ++op)
#pragma unroll
        for (int q = 0; q < 4; ++q) acc[op][q] = __half2half2(__ushort_as_half(0));

    // ic-outer mainloop: transient 16 dup-packed inputs, then 9 taps x 64 oc
#pragma unroll 1
    for (int ic = 0; ic < IC1; ++ic) {
        uint32_t hd[16];
#pragma unroll
        for (int i = 0; i < 4; ++i) {
            const float2* p = (const float2*)&s_in[ic * 612 + (rr + i) * 34 + cc];
            float2 u = p[0], w = p[1];
            float rv[4] = {u.x, u.y, w.x, w.y};
#pragma unroll
            for (int j = 0; j < 4; ++j) {
                __half2 h = __half2half2(__float2half_rn(rv[j]));
                hd[i * 4 + j] = *reinterpret_cast<uint32_t*>(&h);
            }
        }
#pragma unroll
        for (int k = 0; k < 9; ++k) {
            const int ky = k / 3, kx = k % 3;
            __half2 v00 = *reinterpret_cast<__half2*>(&hd[ky * 4 + kx]);
            __half2 v01 = *reinterpret_cast<__half2*>(&hd[ky * 4 + kx + 1]);
            __half2 v10 = *reinterpret_cast<__half2*>(&hd[(ky + 1) * 4 + kx]);
            __half2 v11 = *reinterpret_cast<__half2*>(&hd[(ky + 1) * 4 + kx + 1]);
#pragma unroll
            for (int p4 = 0; p4 < 8; ++p4) {
                uint4 wv = s_wp4[(ic * 9 + k) * 8 + p4];
                uint32_t wq[4] = {wv.x, wv.y, wv.z, wv.w};
#pragma unroll
                for (int j = 0; j < 4; ++j) {
                    const int op = p4 * 4 + j;
                    __half2 w = *reinterpret_cast<__half2*>(&wq[j]);
                    acc[op][0] = __hfma2(w, v00, acc[op][0]);
                    acc[op][1] = __hfma2(w, v01, acc[op][1]);
                    acc[op][2] = __hfma2(w, v10, acc[op][2]);
                    acc[op][3] = __hfma2(w, v11, acc[op][3]);
                }
            }
        }
    }

    // epilogue (once): BN + pool max + margin classify per oc
#pragma unroll
    for (int op = 0; op < 32; ++op) {
        float lo[4], hi[4];
#pragma unroll
        for (int q = 0; q < 4; ++q) {
            lo[q] = __low2float(acc[op][q]);
            hi[q] = __high2float(acc[op][q]);
        }
#pragma unroll
        for (int s2 = 0; s2 < 2; ++s2) {
            const int oc = 2 * op + s2;
            const float* v = s2 ? hi : lo;
            float mx = fmaxf(fmaxf(v[0], v[1]), fmaxf(v[2], v[3]));
            float mn = fminf(fminf(v[0], v[1]), fminf(v[2], v[3]));
            float inv = __ldg(&g_inv1[oc]);
            float bet = __ldg(&g_beta1[oc]);
            float zb = (inv >= 0.f ? mx : mn) * inv + bet;
            float Mz = M0 * fabsf(inv);
            unsigned char s = 0;
            if (zb - Mz > 1.0f) s = 1;
            else if (zb + Mz > 1.0f) {
                int ix = atomicAdd(&sLC[0], 1);
                sList[ix] = (uint16_t)(tid * 64 + oc);
            }
            spk[oc * 128 + tid] = s;
        }
    }
    __syncthreads();

    // exact fp32 fixup of ambiguous windows from the staged fp32 tile
    {
        const int cnt = sLC[0];
        for (int i = tid; i < cnt; i += 128) {
            const int e = sList[i];
            const int q = e >> 6, oc = e & 63;
            const int r0 = 2 * (q >> 4), c0 = 2 * (q & 15);
            float a0 = 0.f, a1 = 0.f, a2 = 0.f, a3 = 0.f;
#pragma unroll 1
            for (int ic = 0; ic < IC1; ++ic) {
                float v[4][4];
#pragma unroll
                for (int iy = 0; iy < 4; ++iy)
#pragma unroll
                    for (int ixx = 0; ixx < 4; ++ixx)
                        v[iy][ixx] = s_in[ic * 612 + (r0 + iy) * 34 + (c0 + ixx)];
                const float* wr = w1 + oc * 90 + ic * 9;
#pragma unroll
                for (int ky = 0; ky < 3; ++ky)
#pragma unroll
                    for (int kx = 0; kx < 3; ++kx) {
                        float wv = __ldg(&wr[ky * 3 + kx]);
                        a0 = fmaf(wv, v[ky][kx],         a0);
                        a1 = fmaf(wv, v[ky][kx + 1],     a1);
                        a2 = fmaf(wv, v[ky + 1][kx],     a2);
                        a3 = fmaf(wv, v[ky + 1][kx + 1], a3);
                    }
            }
            const float inv = __ldg(&g_inv1[oc]), bet = __ldg(&g_beta1[oc]);
            float zm = fmaxf(fmaxf(fmaf(a0, inv, bet), fmaf(a1, inv, bet)),
                             fmaxf(fmaf(a2, inv, bet), fmaf(a3, inv, bet)));
            spk[oc * 128 + q] = (zm > 1.0f);
        }
    }
    __syncthreads();

    // reduce spike map -> the 9 aggregates
    if (tid < 64) {
        const int oc = tid;
        const int* row = (const int*)&spk[oc * 128];
        int S = 0;
#pragma unroll
        for (int j = 0; j < 32; ++j) S = __dp4a(row[j], 0x01010101, S);
        if (S) atomicAdd(&g_cnt[n][oc][0], S);
        if (by == 0) {      // pooled row 0 lives at lpy==0 -> q 0..15
            int Rf = 0;
#pragma unroll
            for (int j = 0; j < 4; ++j) Rf = __dp4a(row[j], 0x01010101, Rf);
            if (Rf) atomicAdd(&g_cnt[n][oc][1], Rf);
        }
        if (by == 15) {     // pooled row 127 at lpy==7 -> q 112..127
            int Rl = 0;
#pragma unroll
            for (int j = 28; j < 32; ++j) Rl = __dp4a(row[j], 0x01010101, Rl);
            if (Rl) atomicAdd(&g_cnt[n][oc][2], Rl);
        }
        if (bx == 0) {      // col 0 at lpx==0 -> q = 16*lpy
            int Cf = 0;
#pragma unroll
            for (int j = 0; j < 8; ++j) Cf += spk[oc * 128 + 16 * j];
            if (Cf) atomicAdd(&g_cnt[n][oc][3], Cf);
        }
        if (bx == 7) {      // col 127 at lpx==15 -> q = 16*lpy + 15
            int Cl = 0;
#pragma unroll
            for (int j = 0; j < 8; ++j) Cl += spk[oc * 128 + 16 * j + 15];
            if (Cl) atomicAdd(&g_cnt[n][oc][4], Cl);
        }
        if (by == 0 && bx == 0 && spk[oc * 128 + 0])     g_cnt[n][oc][5] = 1;
        if (by == 0 && bx == 7 && spk[oc * 128 + 15])    g_cnt[n][oc][6] = 1;
        if (by == 15 && bx == 0 && spk[oc * 128 + 112])  g_cnt[n][oc][7] = 1;
        if (by == 15 && bx == 7 && spk[oc * 128 + 127])  g_cnt[n][oc][8] = 1;
    }
}

// ---------------------------------------------------------------------------
// stage B: analytic conv2-mean via T aggregates, BN2, spike -> g_s2
// ---------------------------------------------------------------------------
__global__ __launch_bounds__(256) void stageB_kernel(const float* __restrict__ w2) {
    __shared__ __align__(16) float sT[OC1 * 9];
    const int n = blockIdx.x, tid = threadIdx.x;
    const int lane = tid & 31, warp = tid >> 5;
    if (tid < OC1) {
        const int* c = g_cnt[n][tid];
        int S = c[0], Rf = c[1], Rl = c[2], Cf = c[3], Cl = c[4];
        int Re[3] = {Rl, 0, Rf};
        int Ce[3] = {Cl, 0, Cf};
        int Q[9]  = {c[8], 0, c[7],  0, 0, 0,  c[6], 0, c[5]};
#pragma unroll
        for (int k = 0; k < 9; ++k)
            sT[tid * 9 + k] = (float)(S - Re[k / 3] - Ce[k % 3] + Q[k]);
    }
    __syncthreads();
#pragma unroll 1
    for (int i = 0; i < 16; ++i) {
        const int o = warp * 16 + i;
        const float* wr = w2 + o * 576;
        float acc = 0.f;
#pragma unroll
        for (int t = 0; t < 18; ++t) {
            int j = t * 32 + lane;
            acc = fmaf(__ldg(&wr[j]), sT[j], acc);
        }
#pragma unroll
        for (int s = 16; s; s >>= 1) acc += __shfl_xor_sync(0xffffffffu, acc, s);
        if (lane == 0) {
            float z = acc * (1.f / 16384.f);
            z = z * g_inv2[o] + g_beta2[o];
            g_s2[n][o] = (z > 1.f) ? 1.f : 0.f;
        }
    }
}

// ---------------------------------------------------------------------------
// stage C: feat = |s0 - s1|, fc1+relu, fc2  -> out (32,5)
// ---------------------------------------------------------------------------
__global__ __launch_bounds__(256) void stageC_kernel(const float* __restrict__ fc1w,
                                                     const float* __restrict__ fc1b,
                                                     const float* __restrict__ fc2w,
                                                     const float* __restrict__ fc2b,
                                                     float* __restrict__ out) {
    __shared__ float f[128];
    __shared__ float h[64];
    const int n = blockIdx.x, tid = threadIdx.x;
    const int lane = tid & 31, warp = tid >> 5;
    if (tid < 128) f[tid] = fabsf(g_s2[n][tid] - g_s2[n + 32][tid]);
    __syncthreads();
#pragma unroll 1
    for (int i = 0; i < 8; ++i) {
        const int k = warp * 8 + i;
        const float* wr = fc1w + k * 128;
        float acc = 0.f;
#pragma unroll
        for (int t = 0; t < 4; ++t) {
            int j = t * 32 + lane;
            acc = fmaf(__ldg(&wr[j]), f[j], acc);
        }
#pragma unroll
        for (int s = 16; s; s >>= 1) acc += __shfl_xor_sync(0xffffffffu, acc, s);
        if (lane == 0) h[k] = fmaxf(acc + fc1b[k], 0.f);
    }
    __syncthreads();
    if (warp == 0) {
#pragma unroll 1
        for (int c = 0; c < 5; ++c) {
            const float* wr = fc2w + c * 64;
            float acc = fmaf(__ldg(&wr[lane]), h[lane], 0.f);
            acc = fmaf(__ldg(&wr[lane + 32]), h[lane + 32], acc);
#pragma unroll
            for (int s = 16; s; s >>= 1) acc += __shfl_xor_sync(0xffffffffu, acc, s);
            if (lane == 0) out[n * 5 + c] = acc + fc2b[c];
        }
    }
}

extern "C" void kernel_launch(void* const* d_in, const int* in_sizes, int n_in,
                              void* d_out, int out_size) {
    const float* x0   = (const float*)d_in[0];
    const float* x1   = (const float*)d_in[1];
    const float* w1   = (const float*)d_in[2];
    const float* b1g  = (const float*)d_in[3];
    const float* b1b  = (const float*)d_in[4];
    const float* b1m  = (const float*)d_in[5];
    const float* b1v  = (const float*)d_in[6];
    const float* w2   = (const float*)d_in[7];
    const float* b2g  = (const float*)d_in[8];
    const float* b2b  = (const float*)d_in[9];
    const float* b2m  = (const float*)d_in[10];
    const float* b2v  = (const float*)d_in[11];
    const float* fc1w = (const float*)d_in[12];
    const float* fc1b = (const float*)d_in[13];
    const float* fc2w = (const float*)d_in[14];
    const float* fc2b = (const float*)d_in[15];

    cudaFuncSetAttribute(stageA_kernel,
                         cudaFuncAttributeMaxDynamicSharedMemorySize, SMEM_BYTES);

    prep_kernel<<<32, 256>>>(w1, b1g, b1b, b1m, b1v, b2g, b2b, b2m, b2v);
    nop_kernel<<<1, 32>>>();   // shim: put stageA in ncu's profiled (4th) slot
    nop_kernel<<<1, 32>>>();
    dim3 gridA(8, 16, 64);
    stageA_kernel<<<gridA, 128, SMEM_BYTES>>>(x0, x1, w1);
    stageB_kernel<<<64, 256>>>(w2);
    stageC_kernel<<<32, 256>>>(fc1w, fc1b, fc2w, fc2b, (float*)d_out);
}

// round 17
// speedup vs baseline: 1.3490x; 1.0265x over previous
#include <cuda_runtime.h>
#include <cuda_fp16.h>
#include <cstdint>

#define IC1 10
#define OC1 64
#define OC2 128
#define NB  64          // 2 images x 32 batch
#define M0  0.03f       // pre-BN ambiguity margin for fp16 accumulation

__device__ int      g_cnt[NB][OC1][9];   // S, Rf, Rl, Cf, Cl, q_tl, q_tr, q_bl, q_br
__device__ float    g_s2[NB][OC2];
__device__ float    g_inv1[OC1],  g_beta1[OC1];
__device__ float    g_inv2[OC2],  g_beta2[OC2];
__device__ __align__(16) uint32_t g_Wp[90 * 32];  // half2 oc-pairs (w[2o],w[2o+1]), [tap][ocpair]

// dynamic smem layout (bytes)
#define SM_W    0        // u32[90*32] = 11520
#define SM_IN   11520    // float[6120] = 24480
#define SM_SPK  36000    // uchar[64*128] = 8192
#define SM_LC   44192    // int[4]
#define SM_LIST 44208    // u16[8192] = 16384 (worst-case exact capacity)
#define SMEM_BYTES 60592

// ---------------------------------------------------------------------------
// nop kernel (launch-slot shims so ncu's 4th-kernel profile lands on stageA)
// ---------------------------------------------------------------------------
__global__ void nop_kernel() {}

// ---------------------------------------------------------------------------
// prep: zero counters, fold BN params, build half2 oc-pair weight table
// ---------------------------------------------------------------------------
__global__ void prep_kernel(const float* __restrict__ w1,
                            const float* __restrict__ g1, const float* __restrict__ b1,
                            const float* __restrict__ m1, const float* __restrict__ v1,
                            const float* __restrict__ g2, const float* __restrict__ b2,
                            const float* __restrict__ m2, const float* __restrict__ v2) {
    int gid = blockIdx.x * blockDim.x + threadIdx.x;
    int* c = &g_cnt[0][0][0];
    for (int i = gid; i < NB * OC1 * 9; i += gridDim.x * blockDim.x) c[i] = 0;
    if (blockIdx.x == 0) {
        int t = threadIdx.x;
        if (t < OC1) {
            float inv = g1[t] / sqrtf(v1[t] + 1e-5f);
            g_inv1[t] = inv;
            g_beta1[t] = b1[t] - m1[t] * inv;
        }
        if (t < OC2) {
            float inv = g2[t] / sqrtf(v2[t] + 1e-5f);
            g_inv2[t] = inv;
            g_beta2[t] = b2[t] - m2[t] * inv;
        }
    }
    if (gid < 90 * 32) {
        int r = gid >> 5, op = gid & 31;
        __half h0 = __float2half_rn(__ldg(&w1[(2 * op) * 90 + r]));
        __half h1 = __float2half_rn(__ldg(&w1[(2 * op + 1) * 90 + r]));
        __half2 d = __halves2half2(h0, h1);
        g_Wp[r * 32 + op] = *reinterpret_cast<uint32_t*>(&d);
    }
}

// ---------------------------------------------------------------------------
// stage A: conv1 via HFMA2 — TWO oc-half passes (acc = 64 half2 regs/pass,
//          spill-free). ic-outer inside each pass, transient input dups.
//          BN + maxpool2 + margin spike + exact in-block fp32 fixup.
// grid (8, 16, 64), block 128. Thread = one pooled window for all 64 oc.
// ---------------------------------------------------------------------------
__global__ __launch_bounds__(128, 2) void stageA_kernel(const float* __restrict__ x0,
                                                        const float* __restrict__ x1,
                                                        const float* __restrict__ w1) {
    extern __shared__ char smem[];
    uint32_t*      s_wp  = (uint32_t*)(smem + SM_W);
    float*         s_in  = (float*)(smem + SM_IN);
    unsigned char* spk   = (unsigned char*)(smem + SM_SPK);
    int*           sLC   = (int*)(smem + SM_LC);
    uint16_t*      sList = (uint16_t*)(smem + SM_LIST);

    const int tid = threadIdx.x;
    const int bx = blockIdx.x, by = blockIdx.y, n = blockIdx.z;
    const float* __restrict__ x = (n < 32) ? x0 : x1;
    const int b = n & 31;

    // load oc-pair weight table (2880 u32 = 720 uint4)
    {
        const uint4* gw = (const uint4*)g_Wp;
        uint4* sw4 = (uint4*)s_wp;
        for (int i = tid; i < 720; i += 128) sw4[i] = __ldg(&gw[i]);
    }
    if (tid == 0) sLC[0] = 0;

    // stage input tile fp32 (18 x 34 per ic), SAME zero padding
    const int iy0 = by * 16 - 1;
    const int ix0 = bx * 32 - 1;
    for (int i = tid; i < IC1 * 612; i += 128) {
        int ic = i / 612, r2 = i % 612;
        int rw = r2 / 34, cl = r2 % 34;
        int gy = iy0 + rw, gx = ix0 + cl;
        float v = 0.f;
        if ((unsigned)gy < 256u && (unsigned)gx < 256u)
            v = __ldg(&x[((b * IC1 + ic) * 256 + gy) * 256 + gx]);
        s_in[i] = v;
    }
    __syncthreads();

    const int lpx = tid & 15, lpy = tid >> 4;
    const int rr = 2 * lpy, cc = 2 * lpx;
    const uint4* s_wp4 = (const uint4*)s_wp;

    // two oc-half passes: 16 oc-pairs each -> acc = 64 half2 regs (spill-free)
#pragma unroll 1
    for (int ph = 0; ph < 2; ++ph) {
        __half2 acc[16][4];
#pragma unroll
        for (int op = 0; op < 16; ++op)
#pragma unroll
            for (int q = 0; q < 4; ++q) acc[op][q] = __half2half2(__ushort_as_half(0));

#pragma unroll 1
        for (int ic = 0; ic < IC1; ++ic) {
            uint32_t hd[16];
#pragma unroll
            for (int i = 0; i < 4; ++i) {
                const float2* p = (const float2*)&s_in[ic * 612 + (rr + i) * 34 + cc];
                float2 u = p[0], w = p[1];
                float rv[4] = {u.x, u.y, w.x, w.y};
#pragma unroll
                for (int j = 0; j < 4; ++j) {
                    __half2 h = __half2half2(__float2half_rn(rv[j]));
                    hd[i * 4 + j] = *reinterpret_cast<uint32_t*>(&h);
                }
            }
#pragma unroll
            for (int k = 0; k < 9; ++k) {
                const int ky = k / 3, kx = k % 3;
                __half2 v00 = *reinterpret_cast<__half2*>(&hd[ky * 4 + kx]);
                __half2 v01 = *reinterpret_cast<__half2*>(&hd[ky * 4 + kx + 1]);
                __half2 v10 = *reinterpret_cast<__half2*>(&hd[(ky + 1) * 4 + kx]);
                __half2 v11 = *reinterpret_cast<__half2*>(&hd[(ky + 1) * 4 + kx + 1]);
#pragma unroll
                for (int p4 = 0; p4 < 4; ++p4) {
                    uint4 wv = s_wp4[(ic * 9 + k) * 8 + ph * 4 + p4];
                    uint32_t wq[4] = {wv.x, wv.y, wv.z, wv.w};
#pragma unroll
                    for (int j = 0; j < 4; ++j) {
                        const int op = p4 * 4 + j;
                        __half2 w = *reinterpret_cast<__half2*>(&wq[j]);
                        acc[op][0] = __hfma2(w, v00, acc[op][0]);
                        acc[op][1] = __hfma2(w, v01, acc[op][1]);
                        acc[op][2] = __hfma2(w, v10, acc[op][2]);
                        acc[op][3] = __hfma2(w, v11, acc[op][3]);
                    }
                }
            }
        }

        // epilogue for this half: BN + pool max + margin classify
#pragma unroll
        for (int op = 0; op < 16; ++op) {
            float lo[4], hi[4];
#pragma unroll
            for (int q = 0; q < 4; ++q) {
                lo[q] = __low2float(acc[op][q]);
                hi[q] = __high2float(acc[op][q]);
            }
#pragma unroll
            for (int s2 = 0; s2 < 2; ++s2) {
                const int oc = ph * 32 + 2 * op + s2;
                const float* v = s2 ? hi : lo;
                float mx = fmaxf(fmaxf(v[0], v[1]), fmaxf(v[2], v[3]));
                float mn = fminf(fminf(v[0], v[1]), fminf(v[2], v[3]));
                float inv = __ldg(&g_inv1[oc]);
                float bet = __ldg(&g_beta1[oc]);
                float zb = (inv >= 0.f ? mx : mn) * inv + bet;
                float Mz = M0 * fabsf(inv);
                unsigned char s = 0;
                if (zb - Mz > 1.0f) s = 1;
                else if (zb + Mz > 1.0f) {
                    int ix = atomicAdd(&sLC[0], 1);
                    sList[ix] = (uint16_t)(tid * 64 + oc);
                }
                spk[oc * 128 + tid] = s;
            }
        }
    }
    __syncthreads();

    // exact fp32 fixup of ambiguous windows from the staged fp32 tile
    {
        const int cnt = sLC[0];
        for (int i = tid; i < cnt; i += 128) {
            const int e = sList[i];
            const int q = e >> 6, oc = e & 63;
            const int r0 = 2 * (q >> 4), c0 = 2 * (q & 15);
            float a0 = 0.f, a1 = 0.f, a2 = 0.f, a3 = 0.f;
#pragma unroll 1
            for (int ic = 0; ic < IC1; ++ic) {
                float v[4][4];
#pragma unroll
                for (int iy = 0; iy < 4; ++iy)
#pragma unroll
                    for (int ixx = 0; ixx < 4; ++ixx)
                        v[iy][ixx] = s_in[ic * 612 + (r0 + iy) * 34 + (c0 + ixx)];
                const float* wr = w1 + oc * 90 + ic * 9;
#pragma unroll
                for (int ky = 0; ky < 3; ++ky)
#pragma unroll
                    for (int kx = 0; kx < 3; ++kx) {
                        float wv = __ldg(&wr[ky * 3 + kx]);
                        a0 = fmaf(wv, v[ky][kx],         a0);
                        a1 = fmaf(wv, v[ky][kx + 1],     a1);
                        a2 = fmaf(wv, v[ky + 1][kx],     a2);
                        a3 = fmaf(wv, v[ky + 1][kx + 1], a3);
                    }
            }
            const float inv = __ldg(&g_inv1[oc]), bet = __ldg(&g_beta1[oc]);
            float zm = fmaxf(fmaxf(fmaf(a0, inv, bet), fmaf(a1, inv, bet)),
                             fmaxf(fmaf(a2, inv, bet), fmaf(a3, inv, bet)));
            spk[oc * 128 + q] = (zm > 1.0f);
        }
    }
    __syncthreads();

    // reduce spike map -> the 9 aggregates
    if (tid < 64) {
        const int oc = tid;
        const int* row = (const int*)&spk[oc * 128];
        int S = 0;
#pragma unroll
        for (int j = 0; j < 32; ++j) S = __dp4a(row[j], 0x01010101, S);
        if (S) atomicAdd(&g_cnt[n][oc][0], S);
        if (by == 0) {      // pooled row 0 lives at lpy==0 -> q 0..15
            int Rf = 0;
#pragma unroll
            for (int j = 0; j < 4; ++j) Rf = __dp4a(row[j], 0x01010101, Rf);
            if (Rf) atomicAdd(&g_cnt[n][oc][1], Rf);
        }
        if (by == 15) {     // pooled row 127 at lpy==7 -> q 112..127
            int Rl = 0;
#pragma unroll
            for (int j = 28; j < 32; ++j) Rl = __dp4a(row[j], 0x01010101, Rl);
            if (Rl) atomicAdd(&g_cnt[n][oc][2], Rl);
        }
        if (bx == 0) {      // col 0 at lpx==0 -> q = 16*lpy
            int Cf = 0;
#pragma unroll
            for (int j = 0; j < 8; ++j) Cf += spk[oc * 128 + 16 * j];
            if (Cf) atomicAdd(&g_cnt[n][oc][3], Cf);
        }
        if (bx == 7) {      // col 127 at lpx==15 -> q = 16*lpy + 15
            int Cl = 0;
#pragma unroll
            for (int j = 0; j < 8; ++j) Cl += spk[oc * 128 + 16 * j + 15];
            if (Cl) atomicAdd(&g_cnt[n][oc][4], Cl);
        }
        if (by == 0 && bx == 0 && spk[oc * 128 + 0])     g_cnt[n][oc][5] = 1;
        if (by == 0 && bx == 7 && spk[oc * 128 + 15])    g_cnt[n][oc][6] = 1;
        if (by == 15 && bx == 0 && spk[oc * 128 + 112])  g_cnt[n][oc][7] = 1;
        if (by == 15 && bx == 7 && spk[oc * 128 + 127])  g_cnt[n][oc][8] = 1;
    }
}

// ---------------------------------------------------------------------------
// stage B: analytic conv2-mean via T aggregates, BN2, spike -> g_s2
// ---------------------------------------------------------------------------
__global__ __launch_bounds__(256) void stageB_kernel(const float* __restrict__ w2) {
    __shared__ __align__(16) float sT[OC1 * 9];
    const int n = blockIdx.x, tid = threadIdx.x;
    const int lane = tid & 31, warp = tid >> 5;
    if (tid < OC1) {
        const int* c = g_cnt[n][tid];
        int S = c[0], Rf = c[1], Rl = c[2], Cf = c[3], Cl = c[4];
        int Re[3] = {Rl, 0, Rf};
        int Ce[3] = {Cl, 0, Cf};
        int Q[9]  = {c[8], 0, c[7],  0, 0, 0,  c[6], 0, c[5]};
#pragma unroll
        for (int k = 0; k < 9; ++k)
            sT[tid * 9 + k] = (float)(S - Re[k / 3] - Ce[k % 3] + Q[k]);
    }
    __syncthreads();
#pragma unroll 1
    for (int i = 0; i < 16; ++i) {
        const int o = warp * 16 + i;
        const float* wr = w2 + o * 576;
        float acc = 0.f;
#pragma unroll
        for (int t = 0; t < 18; ++t) {
            int j = t * 32 + lane;
            acc = fmaf(__ldg(&wr[j]), sT[j], acc);
        }
#pragma unroll
        for (int s = 16; s; s >>= 1) acc += __shfl_xor_sync(0xffffffffu, acc, s);
        if (lane == 0) {
            float z = acc * (1.f / 16384.f);
            z = z * g_inv2[o] + g_beta2[o];
            g_s2[n][o] = (z > 1.f) ? 1.f : 0.f;
        }
    }
}

// ---------------------------------------------------------------------------
// stage C: feat = |s0 - s1|, fc1+relu, fc2  -> out (32,5)
// ---------------------------------------------------------------------------
__global__ __launch_bounds__(256) void stageC_kernel(const float* __restrict__ fc1w,
                                                     const float* __restrict__ fc1b,
                                                     const float* __restrict__ fc2w,
                                                     const float* __restrict__ fc2b,
                                                     float* __restrict__ out) {
    __shared__ float f[128];
    __shared__ float h[64];
    const int n = blockIdx.x, tid = threadIdx.x;
    const int lane = tid & 31, warp = tid >> 5;
    if (tid < 128) f[tid] = fabsf(g_s2[n][tid] - g_s2[n + 32][tid]);
    __syncthreads();
#pragma unroll 1
    for (int i = 0; i < 8; ++i) {
        const int k = warp * 8 + i;
        const float* wr = fc1w + k * 128;
        float acc = 0.f;
#pragma unroll
        for (int t = 0; t < 4; ++t) {
            int j = t * 32 + lane;
            acc = fmaf(__ldg(&wr[j]), f[j], acc);
        }
#pragma unroll
        for (int s = 16; s; s >>= 1) acc += __shfl_xor_sync(0xffffffffu, acc, s);
        if (lane == 0) h[k] = fmaxf(acc + fc1b[k], 0.f);
    }
    __syncthreads();
    if (warp == 0) {
#pragma unroll 1
        for (int c = 0; c < 5; ++c) {
            const float* wr = fc2w + c * 64;
            float acc = fmaf(__ldg(&wr[lane]), h[lane], 0.f);
            acc = fmaf(__ldg(&wr[lane + 32]), h[lane + 32], acc);
#pragma unroll
            for (int s = 16; s; s >>= 1) acc += __shfl_xor_sync(0xffffffffu, acc, s);
            if (lane == 0) out[n * 5 + c] = acc + fc2b[c];
        }
    }
}

extern "C" void kernel_launch(void* const* d_in, const int* in_sizes, int n_in,
                              void* d_out, int out_size) {
    const float* x0   = (const float*)d_in[0];
    const float* x1   = (const float*)d_in[1];
    const float* w1   = (const float*)d_in[2];
    const float* b1g  = (const float*)d_in[3];
    const float* b1b  = (const float*)d_in[4];
    const float* b1m  = (const float*)d_in[5];
    const float* b1v  = (const float*)d_in[6];
    const float* w2   = (const float*)d_in[7];
    const float* b2g  = (const float*)d_in[8];
    const float* b2b  = (const float*)d_in[9];
    const float* b2m  = (const float*)d_in[10];
    const float* b2v  = (const float*)d_in[11];
    const float* fc1w = (const float*)d_in[12];
    const float* fc1b = (const float*)d_in[13];
    const float* fc2w = (const float*)d_in[14];
    const float* fc2b = (const float*)d_in[15];

    cudaFuncSetAttribute(stageA_kernel,
                         cudaFuncAttributeMaxDynamicSharedMemorySize, SMEM_BYTES);

    prep_kernel<<<32, 256>>>(w1, b1g, b1b, b1m, b1v, b2g, b2b, b2m, b2v);
    nop_kernel<<<1, 32>>>();   // shim: put stageA in ncu's profiled (4th) slot
    nop_kernel<<<1, 32>>>();
    dim3 gridA(8, 16, 64);
    stageA_kernel<<<gridA, 128, SMEM_BYTES>>>(x0, x1, w1);
    stageB_kernel<<<64, 256>>>(w2);
    stageC_kernel<<<32, 256>>>(fc1w, fc1b, fc2w, fc2b, (float*)d_out);
}